// round 7
// baseline (speedup 1.0000x reference)
#include <cuda_runtime.h>
#include <cstdint>

#define NN 100000
#define PP 250000
#define PPB 256
#define NTHREADS 256

__device__ float g_fd[NN * 16];   // degree-gate values, recomputed every call

// Packed Blackwell f32x2 ops (only reachable via inline PTX)
#define FMAX2(acc, a, b) \
    asm("fma.rn.f32x2 %0, %1, %2, %0;" : "+l"(acc) : "l"(a), "l"(b))
#define ADD2(acc, b) \
    asm("add.rn.f32x2 %0, %0, %1;" : "+l"(acc) : "l"(b))
#define PACK2(dst, src) \
    asm("mov.b64 %0, {%1, %1};" : "=l"(dst) : "r"(src))
#define RED4(ptr, a, b, c, d) \
    asm volatile("red.global.add.v4.f32 [%0], {%1,%2,%3,%4};" \
                 :: "l"(ptr), "f"(a), "f"(b), "f"(c), "f"(d) : "memory")

// ---------------------------------------------------------------------------
// Kernel 1: fd[n,c] = relu(degs[n]*W0 + b0) @ W1 + b1 into g_fd; zero d_out.
// ---------------------------------------------------------------------------
__global__ __launch_bounds__(256) void fd_pre_kernel(
    const float* __restrict__ degs,
    const float* __restrict__ W0, const float* __restrict__ b0,
    const float* __restrict__ W1, const float* __restrict__ b1,
    float* __restrict__ out)
{
    __shared__ float sw0[32], sb0[32];
    __shared__ ulonglong2 sw1v[128];
    __shared__ unsigned long long sb1p[8];

    int tid = threadIdx.x;
    if (tid < 32) { sw0[tid] = W0[tid]; sb0[tid] = b0[tid]; }
    if (tid < 128) sw1v[tid] = ((const ulonglong2*)W1)[tid];
    if (tid < 8)  sb1p[tid] = ((const unsigned long long*)b1)[tid];
    __syncthreads();

    int n = blockIdx.x * 256 + tid;
    if (n >= NN) return;

    unsigned long long acc[8];
    #pragma unroll
    for (int i = 0; i < 8; ++i) acc[i] = sb1p[i];

    float dg = degs[n];
    #pragma unroll
    for (int j = 0; j < 32; ++j) {
        float h = fmaxf(fmaf(dg, sw0[j], sb0[j]), 0.f);
        unsigned long long hh; PACK2(hh, __float_as_uint(h));
        const ulonglong2* wp = sw1v + j * 4;
        ulonglong2 wA = wp[0], wB = wp[1], wC = wp[2], wD = wp[3];
        FMAX2(acc[0], hh, wA.x); FMAX2(acc[1], hh, wA.y);
        FMAX2(acc[2], hh, wB.x); FMAX2(acc[3], hh, wB.y);
        FMAX2(acc[4], hh, wC.x); FMAX2(acc[5], hh, wC.y);
        FMAX2(acc[6], hh, wD.x); FMAX2(acc[7], hh, wD.y);
    }

    ulonglong2* fdv = (ulonglong2*)(g_fd + n * 16);
    fdv[0] = make_ulonglong2(acc[0], acc[1]);
    fdv[1] = make_ulonglong2(acc[2], acc[3]);
    fdv[2] = make_ulonglong2(acc[4], acc[5]);
    fdv[3] = make_ulonglong2(acc[6], acc[7]);

    float4 z = make_float4(0.f, 0.f, 0.f, 0.f);
    float4* ov = (float4*)(out + n * 16);
    ov[0] = z; ov[1] = z; ov[2] = z; ov[3] = z;
}

// ---------------------------------------------------------------------------
// Main kernel: 4 rows/thread; merged 16B row records; shuffle-free compute.
// thread (q = tid&3, rb = tid>>2) owns x[d in 4q..4q+4) of rows rb+64r (r<4),
// accumulates PARTIAL y over all 16 c; quad butterfly at end; RED4 scatter.
// W swizzle: 16B chunk cc of row k at slot (cc ^ ((k>>2)&3)) -> conflict-free.
// Record swizzle: row' = row ^ ((l>>1)&7) -> conflict-free STS.128 staging.
// ---------------------------------------------------------------------------
__global__ __launch_bounds__(NTHREADS, 2) void lrp_main_kernel(
    const float* __restrict__ nfeat,
    const void*  __restrict__ efeat_idx,
    const void*  __restrict__ n_row_probe,
    const void*  __restrict__ n_col, const float* __restrict__ n_val,
    const void*  __restrict__ e_col, const float* __restrict__ e_val,
    const void*  __restrict__ p_row, const float* __restrict__ p_val,
    const float* __restrict__ weights, const float* __restrict__ bias,
    const float* __restrict__ bond_emb,
    float* __restrict__ out)
{
    extern __shared__ float smem[];
    float*  sW   = smem;                    // 4096 floats (swizzled)
    float4* sRec = (float4*)(sW + 4096);    // 4096 recs {nc, t, nv, ev}
    float*  sEmb = (float*)(sRec + 4096);   // 64
    float*  sBias= sEmb + 64;               // 16

    const int tid   = threadIdx.x;
    const int pbase = blockIdx.x * PPB;
    const bool i64  = (((const int*)n_row_probe)[1] == 0);

    // ---- stage W transposed + swizzled
    #pragma unroll
    for (int i = tid; i < 4096; i += NTHREADS) {
        int k = i >> 4, c = i & 15;
        int l = k >> 4, d = k & 15;
        int cc = (c >> 2) ^ ((k >> 2) & 3);
        sW[k * 16 + (cc << 2) + (c & 3)] = weights[d * 256 + c * 16 + l];
    }
    if (tid < 64) sEmb[tid]  = bond_emb[tid];
    if (tid < 16) sBias[tid] = bias[tid];

    // ---- stage 4096 m-row records (pairs, coalesced loads; swizzled STS.128)
    const long long mhalf = (long long)pbase * 8;
    #pragma unroll 1
    for (int it = 0; it < 8; ++it) {
        int i  = it * NTHREADS + tid;   // pair idx 0..2047
        int pl = i >> 3;                // p-local row 0..255
        int l  = (i << 1) & 15;         // even l
        int phys = pl ^ ((l >> 1) & 7); // same for l and l+1
        if (pbase + pl < PP) {
            long long nc0, nc1, ec0, ec1;
            if (i64) {
                longlong2 ncp = ((const longlong2*)n_col)[mhalf + i];
                longlong2 ecp = ((const longlong2*)e_col)[mhalf + i];
                nc0 = ncp.x; nc1 = ncp.y; ec0 = ecp.x; ec1 = ecp.y;
            } else {
                int2 ncp = ((const int2*)n_col)[mhalf + i];
                int2 ecp = ((const int2*)e_col)[mhalf + i];
                nc0 = ncp.x; nc1 = ncp.y; ec0 = ecp.x; ec1 = ecp.y;
            }
            int t0 = i64 ? (int)((const long long*)efeat_idx)[ec0]
                         : ((const int*)efeat_idx)[(int)ec0];
            int t1 = i64 ? (int)((const long long*)efeat_idx)[ec1]
                         : ((const int*)efeat_idx)[(int)ec1];
            float2 nvp = ((const float2*)n_val)[mhalf + i];
            float2 evp = ((const float2*)e_val)[mhalf + i];
            sRec[l * 256 + phys] = make_float4(
                __int_as_float((int)nc0), __int_as_float(t0), nvp.x, evp.x);
            sRec[(l + 1) * 256 + phys] = make_float4(
                __int_as_float((int)nc1), __int_as_float(t1), nvp.y, evp.y);
        } else {
            float4 z = make_float4(0.f, 0.f, 0.f, 0.f);
            sRec[l * 256 + phys] = z;
            sRec[(l + 1) * 256 + phys] = z;
        }
    }
    __syncthreads();    // the only block-wide barrier

    const int q  = tid & 3;
    const int rb = tid >> 2;           // 0..63; rows rb + 64r

    const float4* nf4 = (const float4*)nfeat;
    const float4* eb4 = (const float4*)sEmb;
    const ulonglong2* sW2 = (const ulonglong2*)sW;

    unsigned long long acc[4][8];
    #pragma unroll
    for (int r = 0; r < 4; ++r)
        #pragma unroll
        for (int j = 0; j < 8; ++j) acc[r][j] = 0ull;

    float4 gnf[4]; int gt[4]; float gnv[4], gev[4];
    #pragma unroll
    for (int r = 0; r < 4; ++r) {
        float4 rec = sRec[rb + 64 * r];             // l=0: swizzle offset 0
        gt[r]  = __float_as_int(rec.y);
        gnv[r] = rec.z; gev[r] = rec.w;
        gnf[r] = __ldg(&nf4[__float_as_int(rec.x) * 4 + q]);
    }

    #pragma unroll 1
    for (int l = 0; l < 16; ++l) {
        // ---- convert to x (this thread's d-quarter, 4 rows)
        float4 xr[4];
        #pragma unroll
        for (int r = 0; r < 4; ++r) {
            float4 eb = eb4[gt[r] * 4 + q];
            xr[r].x = fmaf(gnv[r], gnf[r].x, gev[r] * eb.x);
            xr[r].y = fmaf(gnv[r], gnf[r].y, gev[r] * eb.y);
            xr[r].z = fmaf(gnv[r], gnf[r].z, gev[r] * eb.z);
            xr[r].w = fmaf(gnv[r], gnf[r].w, gev[r] * eb.w);
        }
        // ---- prefetch next l's records + gathers (latency hidden by compute)
        if (l < 15) {
            int sw = ((l + 1) >> 1) & 7;
            #pragma unroll
            for (int r = 0; r < 4; ++r) {
                float4 rec = sRec[(l + 1) * 256 + ((rb + 64 * r) ^ sw)];
                gt[r]  = __float_as_int(rec.y);
                gnv[r] = rec.z; gev[r] = rec.w;
                gnf[r] = __ldg(&nf4[__float_as_int(rec.x) * 4 + q]);
            }
        }
        // ---- accumulate: own-x, swizzled conflict-free W
        #pragma unroll
        for (int dd = 0; dd < 4; ++dd) {
            const int k = l * 16 + q * 4 + dd;
            unsigned long long a[4];
            #pragma unroll
            for (int r = 0; r < 4; ++r) {
                float comp = (dd == 0) ? xr[r].x : (dd == 1) ? xr[r].y
                           : (dd == 2) ? xr[r].z : xr[r].w;
                PACK2(a[r], __float_as_uint(comp));
            }
            #pragma unroll
            for (int cc = 0; cc < 4; ++cc) {
                ulonglong2 w = sW2[k * 4 + (cc ^ q)];
                FMAX2(acc[0][2 * cc],     a[0], w.x);
                FMAX2(acc[0][2 * cc + 1], a[0], w.y);
                FMAX2(acc[1][2 * cc],     a[1], w.x);
                FMAX2(acc[1][2 * cc + 1], a[1], w.y);
                FMAX2(acc[2][2 * cc],     a[2], w.x);
                FMAX2(acc[2][2 * cc + 1], a[2], w.y);
                FMAX2(acc[3][2 * cc],     a[3], w.x);
                FMAX2(acc[3][2 * cc + 1], a[3], w.y);
            }
        }
    }

    // ---- quad butterfly reduction over d-quarters
    #pragma unroll
    for (int m = 1; m <= 2; m <<= 1) {
        #pragma unroll
        for (int r = 0; r < 4; ++r)
            #pragma unroll
            for (int j = 0; j < 8; ++j) {
                unsigned long long o =
                    __shfl_xor_sync(0xffffffffu, acc[r][j], m, 32);
                ADD2(acc[r][j], o);
            }
    }

    // ---- epilogue: lane q writes c-quarter q of its 4 rows
    float b0 = sBias[4 * q + 0], b1 = sBias[4 * q + 1];
    float b2 = sBias[4 * q + 2], b3 = sBias[4 * q + 3];
    #pragma unroll
    for (int r = 0; r < 4; ++r) {
        int p = pbase + rb + 64 * r;
        if (p >= PP) continue;
        long long pr = i64 ? ((const long long*)p_row)[p]
                           : (long long)((const int*)p_row)[p];
        float pv = p_val[p];
        float4 fd = __ldg((const float4*)(g_fd + pr * 16 + 4 * q));
        unsigned int lo, hi;
        float y0, y1, y2, y3;
        asm("mov.b64 {%0, %1}, %2;" : "=r"(lo), "=r"(hi) : "l"(acc[r][2 * q]));
        y0 = __uint_as_float(lo); y1 = __uint_as_float(hi);
        asm("mov.b64 {%0, %1}, %2;" : "=r"(lo), "=r"(hi) : "l"(acc[r][2 * q + 1]));
        y2 = __uint_as_float(lo); y3 = __uint_as_float(hi);
        float v0 = fmaxf(y0 + b0, 0.f) * pv * fd.x;
        float v1 = fmaxf(y1 + b1, 0.f) * pv * fd.y;
        float v2 = fmaxf(y2 + b2, 0.f) * pv * fd.z;
        float v3 = fmaxf(y3 + b3, 0.f) * pv * fd.w;
        const float* dst = out + pr * 16 + 4 * q;
        RED4(dst, v0, v1, v2, v3);
    }
}

extern "C" void kernel_launch(void* const* d_in, const int* in_sizes, int n_in,
                              void* d_out, int out_size)
{
    const float* nfeat     = (const float*)d_in[0];
    const void*  efeat_idx = d_in[1];
    const void*  n_row     = d_in[2];
    const void*  n_col     = d_in[3];
    const float* n_val     = (const float*)d_in[4];
    const void*  e_col     = d_in[6];
    const float* e_val     = (const float*)d_in[7];
    const void*  p_row     = d_in[8];
    const float* p_val     = (const float*)d_in[10];
    const float* degs      = (const float*)d_in[11];
    const float* weights   = (const float*)d_in[12];
    const float* bias      = (const float*)d_in[13];
    const float* W0        = (const float*)d_in[14];
    const float* b0        = (const float*)d_in[15];
    const float* W1        = (const float*)d_in[16];
    const float* b1        = (const float*)d_in[17];
    const float* bond_emb  = (const float*)d_in[18];
    float* out = (float*)d_out;

    // fd (+ output zeroing) first; main kernel LAST so ncu -s 5 -c 1 captures it
    fd_pre_kernel<<<(NN + 255) / 256, 256>>>(degs, W0, b0, W1, b1, out);

    const int smem_bytes = 4096 * 4 + 4096 * 16 + (64 + 16) * 4;  // 82,240 B
    cudaFuncSetAttribute(lrp_main_kernel,
                         cudaFuncAttributeMaxDynamicSharedMemorySize, smem_bytes);
    int grid = (PP + PPB - 1) / PPB;  // 977
    lrp_main_kernel<<<grid, NTHREADS, smem_bytes>>>(
        nfeat, efeat_idx, n_row, n_col, n_val, e_col, e_val,
        p_row, p_val, weights, bias, bond_emb, out);
}